// round 4
// baseline (speedup 1.0000x reference)
#include <cuda_runtime.h>

// GCN, 4 layers: h' = relu( D^-1/2 (A+I) D^-1/2 (h W) + b )
// Factorization: agg[d] = dinv[d] * ( sum_{(s->d) in E} g[s] + g[d] ),
// where g = (h @ W) * dinv[row].  GEMM epilogue writes g into BOTH the
// g-buffer and the agg-buffer (agg init == self-loop term), so the edge
// scatter is a bare agg[dst] += g[src].

#define NN 100000
#define FD 128

// scratch (static __device__ arrays: no allocation anywhere)
__device__ float g_dinv[NN];
__device__ float g_h[(size_t)NN * FD];    // layer input  (finalized output)
__device__ float g_g[(size_t)NN * FD];    // g = (hW)*dinv[row]
__device__ float g_agg[(size_t)NN * FD];  // atomic accumulator

// ---------------- degree / norm ----------------

__global__ void k_deg_init(int n) {
  int i = blockIdx.x * blockDim.x + threadIdx.x;
  if (i < n) g_dinv[i] = 1.0f;  // self loop
}

__global__ void k_deg_count(const int* __restrict__ dst, int e) {
  int i = blockIdx.x * blockDim.x + threadIdx.x;
  if (i < e) atomicAdd(&g_dinv[dst[i]], 1.0f);
}

__global__ void k_deg_rsqrt(int n) {
  int i = blockIdx.x * blockDim.x + threadIdx.x;
  if (i < n) g_dinv[i] = rsqrtf(g_dinv[i]);  // deg >= 1 always
}

// ---------------- GEMM: g = (A @ B) * dinv[row], dual-store to g_g & g_agg ----
// A: [M,128] row-major.  B: [128,D] row-major (D = 128 or 40, D % 4 == 0).
// 128x128 block tile, BK=8, 8x8 per thread, 256 threads.

__global__ __launch_bounds__(256, 2)
void k_gemm_scale(const float* __restrict__ A, const float* __restrict__ B,
                  int M, int D) {
  const int K = 128;
  __shared__ float As[8][128];
  __shared__ float Bs[8][128];

  int tid = threadIdx.x;
  int bm  = blockIdx.x * 128;
  int tx  = tid & 15;        // 0..15 -> col group (8 cols each)
  int ty  = tid >> 4;        // 0..15 -> row group (8 rows each)

  float acc[8][8];
#pragma unroll
  for (int i = 0; i < 8; i++)
#pragma unroll
    for (int j = 0; j < 8; j++) acc[i][j] = 0.0f;

  // loader mapping: A tile 128x8 (one float4 per thread), B tile 8x128
  int aRow = tid >> 1;            // 0..127
  int aCol = (tid & 1) * 4;       // 0 or 4
  int bRow = tid >> 5;            // 0..7
  int bCol = (tid & 31) * 4;      // 0..124
  bool aIn = (bm + aRow) < M;
  bool bIn = bCol < D;            // D=40: pad Bs with zeros
  const float* Aptr = A + (size_t)(bm + aRow) * K + aCol;

  for (int k0 = 0; k0 < K; k0 += 8) {
    float4 av = aIn ? *(const float4*)(Aptr + k0) : make_float4(0.f, 0.f, 0.f, 0.f);
    As[aCol + 0][aRow] = av.x;
    As[aCol + 1][aRow] = av.y;
    As[aCol + 2][aRow] = av.z;
    As[aCol + 3][aRow] = av.w;

    float4 bv = bIn ? *(const float4*)(B + (size_t)(k0 + bRow) * D + bCol)
                    : make_float4(0.f, 0.f, 0.f, 0.f);
    *(float4*)&Bs[bRow][bCol] = bv;

    __syncthreads();
#pragma unroll
    for (int kk = 0; kk < 8; kk++) {
      float a[8], b[8];
      *(float4*)(a)     = *(const float4*)&As[kk][ty * 8];
      *(float4*)(a + 4) = *(const float4*)&As[kk][ty * 8 + 4];
      *(float4*)(b)     = *(const float4*)&Bs[kk][tx * 8];
      *(float4*)(b + 4) = *(const float4*)&Bs[kk][tx * 8 + 4];
#pragma unroll
      for (int i = 0; i < 8; i++)
#pragma unroll
        for (int j = 0; j < 8; j++) acc[i][j] += a[i] * b[j];
    }
    __syncthreads();
  }

  // epilogue: scale by dinv[row], dual-store (g and agg-init == self-loop term)
#pragma unroll
  for (int i = 0; i < 8; i++) {
    int row = bm + ty * 8 + i;
    if (row >= M) continue;
    float s = g_dinv[row];
#pragma unroll
    for (int j = 0; j < 8; j += 4) {
      int col = tx * 8 + j;
      if (col >= D) continue;
      float4 v;
      v.x = acc[i][j + 0] * s;
      v.y = acc[i][j + 1] * s;
      v.z = acc[i][j + 2] * s;
      v.w = acc[i][j + 3] * s;
      size_t off = (size_t)row * D + col;
      *(float4*)(g_g + off)   = v;
      *(float4*)(g_agg + off) = v;
    }
  }
}

// ---------------- edge scatter: agg[dst] += g[src] ----------------
// one warp per edge; lane handles one float4 of the feature row.

__global__ void k_scatter(const int* __restrict__ src, const int* __restrict__ dst,
                          int E, int D) {
  int w    = (blockIdx.x * blockDim.x + threadIdx.x) >> 5;
  int lane = threadIdx.x & 31;
  if (w >= E) return;
  int s = __ldg(src + w);
  int d = __ldg(dst + w);
  int c = lane * 4;
  if (c < D) {
    float4 v = *(const float4*)(g_g + (size_t)s * D + c);
    float* p = g_agg + (size_t)d * D + c;
    asm volatile("red.global.add.v4.f32 [%0], {%1, %2, %3, %4};"
                 :: "l"(p), "f"(v.x), "f"(v.y), "f"(v.z), "f"(v.w)
                 : "memory");
  }
}

// ---------------- finalize: out = [relu](agg * dinv[row] + b) ----------------

__global__ void k_finalize(const float* __restrict__ bias, float* __restrict__ out,
                           int M, int D, int do_relu) {
  int per_row = D >> 2;                       // float4s per row (D % 4 == 0)
  int t = blockIdx.x * blockDim.x + threadIdx.x;
  if (t >= M * per_row) return;
  int row = t / per_row;
  int c4  = t - row * per_row;
  size_t off = (size_t)row * D + (size_t)c4 * 4;
  float s = g_dinv[row];
  float4 v = *(const float4*)(g_agg + off);
  float4 b = *(const float4*)(bias + c4 * 4);
  v.x = v.x * s + b.x;
  v.y = v.y * s + b.y;
  v.z = v.z * s + b.z;
  v.w = v.w * s + b.w;
  if (do_relu) {
    v.x = fmaxf(v.x, 0.0f);
    v.y = fmaxf(v.y, 0.0f);
    v.z = fmaxf(v.z, 0.0f);
    v.w = fmaxf(v.w, 0.0f);
  }
  *(float4*)(out + off) = v;
}

// ---------------- host launcher ----------------

extern "C" void kernel_launch(void* const* d_in, const int* in_sizes, int n_in,
                              void* d_out, int out_size) {
  const float* x  = (const float*)d_in[0];
  const int*   ei = (const int*)d_in[1];
  const float* W[4] = {(const float*)d_in[2], (const float*)d_in[4],
                       (const float*)d_in[6], (const float*)d_in[8]};
  const float* b[4] = {(const float*)d_in[3], (const float*)d_in[5],
                       (const float*)d_in[7], (const float*)d_in[9]};

  int M = in_sizes[0] / FD;       // 100000
  int E = in_sizes[1] / 2;        // 500000
  const int* src = ei;            // edge_index[0]
  const int* dst = ei + E;        // edge_index[1]

  // norm precompute
  k_deg_init<<<(M + 255) / 256, 256>>>(M);
  k_deg_count<<<(E + 255) / 256, 256>>>(dst, E);
  k_deg_rsqrt<<<(M + 255) / 256, 256>>>(M);

  int gemm_blocks    = (M + 127) / 128;
  int scatter_blocks = (E * 32 + 255) / 256;

  // layers 0-2: D = 128, ReLU
  const float* Ain = x;
  for (int l = 0; l < 3; l++) {
    k_gemm_scale<<<gemm_blocks, 256>>>(Ain, W[l], M, 128);
    k_scatter<<<scatter_blocks, 256>>>(src, dst, E, 128);
    int n4 = M * (128 / 4);
    float* h;
    cudaGetSymbolAddress((void**)&h, g_h);
    k_finalize<<<(n4 + 255) / 256, 256>>>(b[l], h, M, 128, 1);
    Ain = h;
  }

  // layer 3: D = 40, no ReLU, write d_out
  k_gemm_scale<<<gemm_blocks, 256>>>(Ain, W[3], M, 40);
  k_scatter<<<scatter_blocks, 256>>>(src, dst, E, 40);
  int n4 = M * (40 / 4);
  k_finalize<<<(n4 + 255) / 256, 256>>>(b[3], (float*)d_out, M, 40, 0);
}

// round 5
// speedup vs baseline: 1.3459x; 1.3459x over previous
#include <cuda_runtime.h>

// GCN, 4 layers: h' = relu( D^-1/2 (A+I) D^-1/2 (h W) + b )
// agg[d] = dinv[d] * ( sum_{(s->d) in E} g[s] + g[d] ),  g = (h@W)*dinv[row]
// GEMM epilogue dual-stores g into g_g and g_agg (self-loop init).
// The relu(agg*dinv + b) "finalize" of layer l is FUSED into layer l+1's
// A-tile load (each A element is read exactly once: N fits one block tile,
// and each block only touches its own 128 rows of g_agg).

#define NN 100000
#define FD 128

__device__ float g_dinv[NN];
__device__ float g_g[(size_t)NN * FD];    // g = (hW)*dinv[row]
__device__ float g_agg[(size_t)NN * FD];  // atomic accumulator

// ---------------- degree / norm ----------------

__global__ void k_deg_init(int n) {
  int i = blockIdx.x * blockDim.x + threadIdx.x;
  if (i < n) g_dinv[i] = 1.0f;  // self loop
}
__global__ void k_deg_count(const int* __restrict__ dst, int e) {
  int i = blockIdx.x * blockDim.x + threadIdx.x;
  if (i < e) atomicAdd(&g_dinv[dst[i]], 1.0f);
}
__global__ void k_deg_rsqrt(int n) {
  int i = blockIdx.x * blockDim.x + threadIdx.x;
  if (i < n) g_dinv[i] = rsqrtf(g_dinv[i]);
}

// ---------------- GEMM core (packed f32x2 FMA) ----------------
// Tile: 128(M) x TN(N), BK=8, 256 threads, 8x(TN/16) per thread.
// acc kept as packed f32x2 in 64-bit regs; FFMA2 = 2 MACs/instr.

template <int TN>
__device__ __forceinline__ void compute_chunk(
    const float (*Ak)[128], const float (*Bk)[TN], int ty, int tx,
    unsigned long long (&acc)[8][TN / 32]) {
  constexpr int JP = TN / 32;  // f32x2 pairs per thread-row
#pragma unroll
  for (int kk = 0; kk < 8; kk++) {
    float a[8];
    *(float4*)(a)     = *(const float4*)&Ak[kk][ty * 8];
    *(float4*)(a + 4) = *(const float4*)&Ak[kk][ty * 8 + 4];
    unsigned long long bb[4];
    {
      ulonglong2 t0 = *(const ulonglong2*)&Bk[kk][tx * (TN / 16)];
      bb[0] = t0.x; bb[1] = t0.y;
      if (JP == 4) {
        ulonglong2 t1 = *(const ulonglong2*)&Bk[kk][tx * (TN / 16) + 4];
        bb[2] = t1.x; bb[3] = t1.y;
      }
    }
#pragma unroll
    for (int i = 0; i < 8; i++) {
      unsigned long long a2;
      asm("mov.b64 %0, {%1, %1};" : "=l"(a2) : "f"(a[i]));
#pragma unroll
      for (int jp = 0; jp < JP; jp++)
        asm("fma.rn.f32x2 %0, %1, %2, %0;"
            : "+l"(acc[i][jp]) : "l"(a2), "l"(bb[jp]));
    }
  }
}

// A: [M,128] row-major (raw when !FUSE, else raw agg of previous layer:
// transformed on load as relu(agg*dinv[row] + bias[k])).
// B: [128,D] row-major, D <= TN, D % 4 == 0 (Bs zero-padded to TN).
// Epilogue: g = acc * dinv[row], dual-store into g_g and g_agg.
template <int TN, bool FUSE>
__global__ __launch_bounds__(256, 2)
void k_gemm(const float* __restrict__ A, const float* __restrict__ B,
            const float* __restrict__ bias, int M, int D) {
  constexpr int JP = TN / 32;
  __shared__ float As[2][8][128];
  __shared__ float Bs[2][8][TN];

  const int tid = threadIdx.x;
  const int bm  = blockIdx.x * 128;
  const int tx  = tid & 15;
  const int ty  = tid >> 4;

  // A loader: one float4 per thread per chunk (tile 128x8)
  const int aRow = tid >> 1;
  const int aCol = (tid & 1) * 4;
  const int arow = bm + aRow;
  const bool aIn = arow < M;
  const float sA = aIn ? g_dinv[arow] : 0.0f;  // used when FUSE
  const float* Aptr = A + (size_t)arow * 128 + aCol;

  // B loader: tile 8 x TN, one float4 per thread (first 2*TN threads)
  const int bRow = tid / (TN / 4);
  const int bCol = (tid % (TN / 4)) * 4;
  const bool bThread = tid < 2 * TN;
  const bool bIn = bThread && (bCol < D);

  unsigned long long acc[8][JP];
#pragma unroll
  for (int i = 0; i < 8; i++)
#pragma unroll
    for (int jp = 0; jp < JP; jp++) acc[i][jp] = 0ull;

  const float4 zero4 = make_float4(0.f, 0.f, 0.f, 0.f);

#define LOAD_A(k0, av)                                              \
  do {                                                              \
    av = aIn ? *(const float4*)(Aptr + (k0)) : zero4;               \
    if (FUSE && aIn) {                                              \
      float4 bb4 = *(const float4*)(bias + (k0) + aCol);            \
      av.x = fmaxf(av.x * sA + bb4.x, 0.f);                         \
      av.y = fmaxf(av.y * sA + bb4.y, 0.f);                         \
      av.z = fmaxf(av.z * sA + bb4.z, 0.f);                         \
      av.w = fmaxf(av.w * sA + bb4.w, 0.f);                         \
    }                                                               \
  } while (0)

#define STORE_TILES(bi, av, bv)                                     \
  do {                                                              \
    As[bi][aCol + 0][aRow] = av.x;                                  \
    As[bi][aCol + 1][aRow] = av.y;                                  \
    As[bi][aCol + 2][aRow] = av.z;                                  \
    As[bi][aCol + 3][aRow] = av.w;                                  \
    if (bThread) *(float4*)&Bs[bi][bRow][bCol] = bv;                \
  } while (0)

  // prologue: chunk 0 -> buffer 0
  {
    float4 av, bv;
    LOAD_A(0, av);
    bv = bIn ? *(const float4*)(B + (size_t)bRow * D + bCol) : zero4;
    STORE_TILES(0, av, bv);
  }
  __syncthreads();

  int buf = 0;
  for (int k0 = 8; k0 < 128; k0 += 8) {
    float4 av, bv;
    LOAD_A(k0, av);  // prefetch next chunk (hidden under compute)
    bv = bIn ? *(const float4*)(B + (size_t)(k0 + bRow) * D + bCol) : zero4;
    compute_chunk<TN>(As[buf], Bs[buf], ty, tx, acc);
    STORE_TILES(buf ^ 1, av, bv);
    __syncthreads();
    buf ^= 1;
  }
  compute_chunk<TN>(As[buf], Bs[buf], ty, tx, acc);

#undef LOAD_A
#undef STORE_TILES

  // epilogue: scale by dinv[row], dual-store
#pragma unroll
  for (int i = 0; i < 8; i++) {
    int r = bm + ty * 8 + i;
    if (r >= M) continue;
    float s = g_dinv[r];
    float v[2 * JP];
#pragma unroll
    for (int jp = 0; jp < JP; jp++) {
      float lo, hi;
      asm("mov.b64 {%0, %1}, %2;" : "=f"(lo), "=f"(hi) : "l"(acc[i][jp]));
      v[jp * 2]     = lo * s;
      v[jp * 2 + 1] = hi * s;
    }
    const int colBase = tx * (TN / 16);
#pragma unroll
    for (int q = 0; q < JP / 2; q++) {
      int col = colBase + q * 4;
      if (col >= D) continue;
      float4 w = make_float4(v[q * 4], v[q * 4 + 1], v[q * 4 + 2], v[q * 4 + 3]);
      size_t off = (size_t)r * D + col;
      *(float4*)(g_g + off)   = w;
      *(float4*)(g_agg + off) = w;
    }
  }
}

// ---------------- edge scatter: agg[dst] += g[src] ----------------

// D=128: one warp per edge, one float4 per lane.
__global__ void k_scatter(const int* __restrict__ src, const int* __restrict__ dst,
                          int E) {
  int w    = (blockIdx.x * blockDim.x + threadIdx.x) >> 5;
  int lane = threadIdx.x & 31;
  if (w >= E) return;
  int s = __ldg(src + w);
  int d = __ldg(dst + w);
  float4 v = *(const float4*)(g_g + (size_t)s * 128 + lane * 4);
  float* p = g_agg + (size_t)d * 128 + lane * 4;
  asm volatile("red.global.add.v4.f32 [%0], {%1, %2, %3, %4};"
               :: "l"(p), "f"(v.x), "f"(v.y), "f"(v.z), "f"(v.w)
               : "memory");
}

// D=40: one thread per (edge, float4) -> 10 threads/edge, no idle lanes.
__global__ void k_scatter_narrow(const int* __restrict__ src,
                                 const int* __restrict__ dst, int E, int D) {
  int per = D >> 2;
  int t = blockIdx.x * blockDim.x + threadIdx.x;
  if (t >= E * per) return;
  int e = t / per;
  int j = (t - e * per) * 4;
  int s = __ldg(src + e);
  int d = __ldg(dst + e);
  float4 v = *(const float4*)(g_g + (size_t)s * D + j);
  float* p = g_agg + (size_t)d * D + j;
  asm volatile("red.global.add.v4.f32 [%0], {%1, %2, %3, %4};"
               :: "l"(p), "f"(v.x), "f"(v.y), "f"(v.z), "f"(v.w)
               : "memory");
}

// ---------------- final layer output: out = agg * dinv + b ----------------

__global__ void k_finalize(const float* __restrict__ bias, float* __restrict__ out,
                           int M, int D) {
  int per_row = D >> 2;
  int t = blockIdx.x * blockDim.x + threadIdx.x;
  if (t >= M * per_row) return;
  int row = t / per_row;
  int c4  = t - row * per_row;
  size_t off = (size_t)row * D + (size_t)c4 * 4;
  float s = g_dinv[row];
  float4 v = *(const float4*)(g_agg + off);
  float4 b = *(const float4*)(bias + c4 * 4);
  v.x = v.x * s + b.x;
  v.y = v.y * s + b.y;
  v.z = v.z * s + b.z;
  v.w = v.w * s + b.w;
  *(float4*)(out + off) = v;
}

// ---------------- host launcher ----------------

extern "C" void kernel_launch(void* const* d_in, const int* in_sizes, int n_in,
                              void* d_out, int out_size) {
  const float* x  = (const float*)d_in[0];
  const int*   ei = (const int*)d_in[1];
  const float* W[4] = {(const float*)d_in[2], (const float*)d_in[4],
                       (const float*)d_in[6], (const float*)d_in[8]};
  const float* b[4] = {(const float*)d_in[3], (const float*)d_in[5],
                       (const float*)d_in[7], (const float*)d_in[9]};

  int M = in_sizes[0] / FD;  // 100000
  int E = in_sizes[1] / 2;   // 500000
  const int* src = ei;
  const int* dst = ei + E;

  float* agg;
  cudaGetSymbolAddress((void**)&agg, g_agg);

  // norm precompute
  k_deg_init<<<(M + 255) / 256, 256>>>(M);
  k_deg_count<<<(E + 255) / 256, 256>>>(dst, E);
  k_deg_rsqrt<<<(M + 255) / 256, 256>>>(M);

  int GB = (M + 127) / 128;
  int sc_wide   = (E * 32 + 255) / 256;
  int sc_narrow = (E * 10 + 255) / 256;

  // layer 0 (A = x, raw)
  k_gemm<128, false><<<GB, 256>>>(x, W[0], b[0] /*unused*/, M, 128);
  k_scatter<<<sc_wide, 256>>>(src, dst, E);

  // layers 1-2 (A = relu(agg*dinv + b[l-1]), fused into load)
  k_gemm<128, true><<<GB, 256>>>(agg, W[1], b[0], M, 128);
  k_scatter<<<sc_wide, 256>>>(src, dst, E);

  k_gemm<128, true><<<GB, 256>>>(agg, W[2], b[1], M, 128);
  k_scatter<<<sc_wide, 256>>>(src, dst, E);

  // layer 3: D = 40, TN = 64 tile
  k_gemm<64, true><<<GB, 256>>>(agg, W[3], b[2], M, 40);
  k_scatter_narrow<<<sc_narrow, 256>>>(src, dst, E, 40);
  k_finalize<<<(M * 10 + 255) / 256, 256>>>(b[3], (float*)d_out, M, 40);
}